// round 2
// baseline (speedup 1.0000x reference)
#include <cuda_runtime.h>
#include <math.h>

// Pines algorithm, degree N=64.
// Strategy: one thread per point; loop m (order) outer, l (degree) inner.
// Per-column Legendre recurrence needs only 2 live scalars.
// Per-(l,m) constants packed as float4 {n1, -n2, cBar, sBar} in shared memory
// (broadcast LDS.128 per inner iteration; zero divergence: all threads share
// identical (l,m) loop structure).

#define N_DEG 64
#define LDIM  65                 // l,m in 0..64
#define TABN  (LDIM * LDIM)      // 4225 float4 = 67600 B
#define CDIM  67                 // cBar/sBar are (N+3)x(N+3) = 67x67

__device__ float4 g_tab[TABN];
__device__ float  g_diag[N_DEG + 2];   // 66
__device__ float  g_sub [N_DEG + 2];

static __constant__ float c_MU   = 398600441800000.0f;
static __constant__ float c_AREF = 6378136.3f;

// ---------------------------------------------------------------------------
// Prep kernel: build normalization tables (double precision, matching the
// reference's float64 constant computation, then cast to fp32).
// ---------------------------------------------------------------------------
__global__ void pines_prep_kernel(const float* __restrict__ cBar,
                                  const float* __restrict__ sBar)
{
    int tid = blockIdx.x * blockDim.x + threadIdx.x;

    if (tid == 0) {
        // diag = cumprod(f), sub per reference
        double diag = 1.0;
        g_diag[0] = 1.0f;
        g_sub[0]  = 0.0f;
        for (int l = 1; l <= N_DEG + 1; ++l) {
            double kl   = 2.0;
            double klm1 = (l == 1) ? 1.0 : 2.0;
            double f    = sqrt((2.0 * l + 1.0) * kl / (2.0 * l * klm1));
            diag *= f;
            g_diag[l] = (float)diag;
            g_sub[l]  = (float)sqrt(2.0 * l * klm1 / kl);
        }
    }

    for (int i = tid; i < TABN; i += gridDim.x * blockDim.x) {
        int l = i / LDIM;
        int m = i % LDIM;
        double n1 = 0.0, n2 = 0.0;
        if (l >= m + 2) {
            double dl = (double)l, dm = (double)m;
            n1 = sqrt((2.0 * dl + 1.0) * (2.0 * dl - 1.0) /
                      ((dl - dm) * (dl + dm)));
            n2 = sqrt((dl + dm - 1.0) * (2.0 * dl + 1.0) * (dl - dm - 1.0) /
                      ((dl + dm) * (dl - dm) * (2.0 * dl - 3.0)));
        }
        float4 v;
        v.x = (float)n1;
        v.y = (float)(-n2);          // store negated: a = fma(u, n1*a1, (-n2)*a2)
        v.z = cBar[l * CDIM + m];
        v.w = sBar[l * CDIM + m];
        g_tab[i] = v;
    }
}

// ---------------------------------------------------------------------------
// Main kernel: one thread per point.
// ---------------------------------------------------------------------------
__global__ void pines_main_kernel(const float* __restrict__ inp,
                                  float* __restrict__ out, int B)
{
    extern __shared__ float4 sm4[];
    float4* s_tab  = sm4;
    float*  s_diag = (float*)(sm4 + TABN);
    float*  s_sub  = s_diag + (N_DEG + 2);

    for (int i = threadIdx.x; i < TABN; i += blockDim.x)
        s_tab[i] = g_tab[i];
    for (int i = threadIdx.x; i < N_DEG + 2; i += blockDim.x) {
        s_diag[i] = g_diag[i];
        s_sub[i]  = g_sub[i];
    }
    __syncthreads();

    int idx = blockIdx.x * blockDim.x + threadIdx.x;
    if (idx >= B) return;

    float4 v = ((const float4*)inp)[idx];
    float r = v.x, s = v.y, t = v.z, u = v.w;

    float rho  = c_AREF / r;
    float muor = c_MU / r;

    float cre = 1.0f, cim = 0.0f;   // Re/Im of (s + i t)^m
    float rm  = muor;               // (MU/r) * rho^m
    float acc = muor;               // MU/r leading term

    for (int m = 0; m <= N_DEG; ++m) {
        float a2 = s_diag[m];                         // a[m][m]
        float a1 = s_sub[m + 1] * s_diag[m + 1] * u;  // a[m+1][m]
        float rp = rm;                                // (MU/r) rho^m  <-> l=m

        if (m >= 1) {   // l = m contribution (l=0 excluded: plain MU/r term)
            float4 t4 = s_tab[m * LDIM + m];
            float  w  = fmaf(t4.z, cre, t4.w * cim);
            acc = fmaf(rp * a2, w, acc);
        }
        if (m + 1 <= N_DEG) {
            // l = m+1 contribution
            rp *= rho;
            {
                float4 t4 = s_tab[(m + 1) * LDIM + m];
                float  w  = fmaf(t4.z, cre, t4.w * cim);
                acc = fmaf(rp * a1, w, acc);
            }
            // l >= m+2 recurrence
            #pragma unroll 4
            for (int l = m + 2; l <= N_DEG; ++l) {
                rp *= rho;
                float4 t4 = s_tab[l * LDIM + m];
                float  w  = fmaf(t4.z, cre, t4.w * cim);
                float  p  = t4.x * a1;      // n1 * a_{l-1}
                float  q  = t4.y * a2;      // (-n2) * a_{l-2}
                float  a  = fmaf(u, p, q);
                acc = fmaf(rp * a, w, acc);
                a2 = a1;
                a1 = a;
            }
        }

        rm *= rho;
        // (s + i t)^(m+1)
        float nre = fmaf(s, cre, -(t * cim));
        float nim = fmaf(s, cim,   t * cre);
        cre = nre;
        cim = nim;
    }

    out[idx] = -acc;
}

// ---------------------------------------------------------------------------
// Launch
// ---------------------------------------------------------------------------
extern "C" void kernel_launch(void* const* d_in, const int* in_sizes, int n_in,
                              void* d_out, int out_size)
{
    const float* inputs = (const float*)d_in[0];  // [B,4] : r,s,t,u
    const float* cBar   = (const float*)d_in[1];  // [67,67]
    const float* sBar   = (const float*)d_in[2];  // [67,67]
    float*       out    = (float*)d_out;          // [B,1]

    int B = in_sizes[0] / 4;

    const size_t smem = TABN * sizeof(float4) + 2 * (N_DEG + 2) * sizeof(float);
    cudaFuncSetAttribute(pines_main_kernel,
                         cudaFuncAttributeMaxDynamicSharedMemorySize,
                         (int)smem);

    pines_prep_kernel<<<17, 256>>>(cBar, sBar);

    int threads = 256;
    int blocks  = (B + threads - 1) / threads;
    pines_main_kernel<<<blocks, threads, smem>>>(inputs, out, B);
}

// round 3
// speedup vs baseline: 1.1953x; 1.1953x over previous
#include <cuda_runtime.h>
#include <math.h>

// Pines algorithm, degree N=64, B=65536.
// R3: f32x2-packed (FFMA2) main kernel, 2 points/thread; constants stored
// pre-duplicated in smem; parallel fp64 prep (serial cumprod reduced to 65 DMULs).

#define N_DEG 64
#define CDIM  67                          // cBar/sBar are 67x67
#define CS_ENTRIES 2145                   // sum_{m=0..64} (65-m)
#define NN_ENTRIES 2016                   // sum_{m=0..62} (63-m)

typedef unsigned long long u64;

// Packed tables: cs = {c,c,s,s}, nn = {n1,n1,-n2,-n2} per (l,m)
__device__ ulonglong2 g_cs[CS_ENTRIES];
__device__ ulonglong2 g_nn[NN_ENTRIES];
__device__ u64        g_diag2[N_DEG + 2];   // {diag,diag}
__device__ u64        g_sd2  [N_DEG + 2];   // {sub[m+1]*diag[m+1], same}

static __constant__ float c_MU   = 398600441800000.0f;
static __constant__ float c_AREF = 6378136.3f;

// ---------------------------------------------------------------------------
// f32x2 helpers
// ---------------------------------------------------------------------------
__device__ __forceinline__ u64 fma2(u64 a, u64 b, u64 c) {
    u64 d; asm("fma.rn.f32x2 %0, %1, %2, %3;" : "=l"(d) : "l"(a), "l"(b), "l"(c));
    return d;
}
__device__ __forceinline__ u64 mul2(u64 a, u64 b) {
    u64 d; asm("mul.rn.f32x2 %0, %1, %2;" : "=l"(d) : "l"(a), "l"(b));
    return d;
}
__device__ __forceinline__ u64 pack2(float lo, float hi) {
    u64 d; asm("mov.b64 %0, {%1, %2};" : "=l"(d) : "f"(lo), "f"(hi));
    return d;
}
__device__ __forceinline__ void unpack2(u64 v, float& lo, float& hi) {
    asm("mov.b64 {%0, %1}, %2;" : "=f"(lo), "=f"(hi) : "l"(v));
}

__device__ __forceinline__ u64 dupf(float x) {
    unsigned int b = __float_as_uint(x);
    return ((u64)b << 32) | (u64)b;
}

// ---------------------------------------------------------------------------
// Prep: build tables. fp64 for parity with the reference's float64 constants,
// but the sqrt work is fully parallel; only 65 DMULs remain serial.
// ---------------------------------------------------------------------------
__global__ void pines_prep_kernel(const float* __restrict__ cBar,
                                  const float* __restrict__ sBar)
{
    // --- block 0: diag / sd tables ---
    if (blockIdx.x == 0) {
        __shared__ double sf[N_DEG + 2];    // f_l factors
        __shared__ double ssub[N_DEG + 2];  // sub[l]
        int l = threadIdx.x;
        if (l >= 1 && l <= N_DEG + 1) {
            double kl   = 2.0;
            double klm1 = (l == 1) ? 1.0 : 2.0;
            sf[l]   = sqrt((2.0 * l + 1.0) * kl / (2.0 * l * klm1));
            ssub[l] = sqrt(2.0 * l * klm1 / kl);
        }
        __syncthreads();
        if (threadIdx.x == 0) {
            double diag[N_DEG + 2];
            diag[0] = 1.0;
            for (int i = 1; i <= N_DEG + 1; ++i) diag[i] = diag[i - 1] * sf[i];
            for (int m = 0; m <= N_DEG + 1; ++m) {
                g_diag2[m] = dupf((float)diag[m]);
                double sd = (m <= N_DEG) ? ssub[m + 1] * diag[m + 1] : 0.0;
                g_sd2[m]  = dupf((float)sd);
            }
        }
    }

    // --- all blocks: (l,m) table entries ---
    int gid    = blockIdx.x * blockDim.x + threadIdx.x;
    int stride = gridDim.x * blockDim.x;
    for (int i = gid; i < 65 * 65; i += stride) {
        int l = i / 65;
        int m = i % 65;
        if (l < m) continue;
        int csBase = 65 * m - (m * (m - 1)) / 2;
        ulonglong2 cs;
        cs.x = dupf(cBar[l * CDIM + m]);
        cs.y = dupf(sBar[l * CDIM + m]);
        g_cs[csBase + (l - m)] = cs;
        if (l >= m + 2) {
            int nnBase = 63 * m - (m * (m - 1)) / 2;
            double dl = (double)l, dm = (double)m;
            double n1 = sqrt((2.0 * dl + 1.0) * (2.0 * dl - 1.0) /
                             ((dl - dm) * (dl + dm)));
            double n2 = sqrt((dl + dm - 1.0) * (2.0 * dl + 1.0) * (dl - dm - 1.0) /
                             ((dl + dm) * (dl - dm) * (2.0 * dl - 3.0)));
            ulonglong2 nn;
            nn.x = dupf((float)n1);
            nn.y = dupf((float)(-n2));
            g_nn[nnBase + (l - m - 2)] = nn;
        }
    }
}

// ---------------------------------------------------------------------------
// Main kernel: 2 points per thread, all FMAs as packed f32x2.
// ---------------------------------------------------------------------------
__global__ void pines_main_kernel(const float4* __restrict__ inp,
                                  float2* __restrict__ out, int pairs)
{
    extern __shared__ u64 smraw[];
    ulonglong2* s_cs    = (ulonglong2*)smraw;                 // 2145 * 16B
    ulonglong2* s_nn    = s_cs + CS_ENTRIES;                  // 2016 * 16B
    u64*        s_diag2 = (u64*)(s_nn + NN_ENTRIES);          // 66 * 8B
    u64*        s_sd2   = s_diag2 + (N_DEG + 2);              // 66 * 8B

    for (int i = threadIdx.x; i < CS_ENTRIES; i += blockDim.x) s_cs[i] = g_cs[i];
    for (int i = threadIdx.x; i < NN_ENTRIES; i += blockDim.x) s_nn[i] = g_nn[i];
    if (threadIdx.x < N_DEG + 2) {
        s_diag2[threadIdx.x] = g_diag2[threadIdx.x];
        s_sd2[threadIdx.x]   = g_sd2[threadIdx.x];
    }
    __syncthreads();

    int p = blockIdx.x * blockDim.x + threadIdx.x;
    if (p >= pairs) return;

    float4 v0 = inp[2 * p + 0];
    float4 v1 = inp[2 * p + 1];

    float rho0 = c_AREF / v0.x, rho1 = c_AREF / v1.x;
    float mu0  = c_MU  / v0.x, mu1  = c_MU  / v1.x;

    u64 rho2 = pack2(rho0, rho1);
    u64 s2   = pack2(v0.y,  v1.y);
    u64 t2   = pack2(v0.z,  v1.z);
    u64 nt2  = pack2(-v0.z, -v1.z);
    u64 u2   = pack2(v0.w,  v1.w);
    u64 rm2  = pack2(mu0,   mu1);    // (MU/r) * rho^m
    u64 acc2 = rm2;                  // leading MU/r term
    u64 cre2 = pack2(1.0f, 1.0f);
    u64 cim2 = 0ULL;

    int csBase = 0, nnBase = 0;

    #pragma unroll 1
    for (int m = 0; m <= N_DEG; ++m) {
        u64 a2v = s_diag2[m];            // a[m][m]
        u64 a1v = mul2(s_sd2[m], u2);    // a[m+1][m]
        u64 rp2 = rm2;                   // (MU/r) rho^l, starts at l=m
        u64 accC, accS;

        if (m >= 1) {                    // l = m term (l=0 handled by MU/r)
            ulonglong2 cs = s_cs[csBase];
            u64 ra = mul2(rp2, a2v);
            accC = mul2(ra, cs.x);
            accS = mul2(ra, cs.y);
        } else {
            accC = 0ULL; accS = 0ULL;
        }

        if (m < N_DEG) {
            // l = m+1
            rp2 = mul2(rp2, rho2);
            {
                ulonglong2 cs = s_cs[csBase + 1];
                u64 ra = mul2(rp2, a1v);
                accC = fma2(ra, cs.x, accC);
                accS = fma2(ra, cs.y, accS);
            }
            // l >= m+2 recurrence
            const ulonglong2* pcs = s_cs + csBase + 2;
            const ulonglong2* pnn = s_nn + nnBase;
            #pragma unroll 4
            for (int l = m + 2; l <= N_DEG; ++l) {
                ulonglong2 cs = *pcs++;
                ulonglong2 nn = *pnn++;
                rp2 = mul2(rp2, rho2);
                u64 a  = fma2(u2, mul2(nn.x, a1v), mul2(nn.y, a2v));
                u64 ra = mul2(rp2, a);
                accC = fma2(ra, cs.x, accC);
                accS = fma2(ra, cs.y, accS);
                a2v = a1v;
                a1v = a;
            }
        }

        // apply phasor once per column
        acc2 = fma2(cre2, accC, acc2);
        acc2 = fma2(cim2, accS, acc2);

        // advance (s + i t)^m and rho power
        u64 nre = fma2(s2, cre2, mul2(nt2, cim2));
        u64 nim = fma2(s2, cim2, mul2(t2,  cre2));
        cre2 = nre;
        cim2 = nim;
        rm2  = mul2(rm2, rho2);

        csBase += 65 - m;
        nnBase += 63 - m;
    }

    float lo, hi;
    unpack2(acc2, lo, hi);
    out[p] = make_float2(-lo, -hi);
}

// ---------------------------------------------------------------------------
// Launch
// ---------------------------------------------------------------------------
extern "C" void kernel_launch(void* const* d_in, const int* in_sizes, int n_in,
                              void* d_out, int out_size)
{
    const float* inputs = (const float*)d_in[0];  // [B,4] : r,s,t,u
    const float* cBar   = (const float*)d_in[1];  // [67,67]
    const float* sBar   = (const float*)d_in[2];  // [67,67]
    float*       out    = (float*)d_out;          // [B]

    int B     = in_sizes[0] / 4;
    int pairs = B / 2;

    const size_t smem = CS_ENTRIES * sizeof(ulonglong2)
                      + NN_ENTRIES * sizeof(ulonglong2)
                      + 2 * (N_DEG + 2) * sizeof(u64);   // 67,632 B
    cudaFuncSetAttribute(pines_main_kernel,
                         cudaFuncAttributeMaxDynamicSharedMemorySize,
                         (int)smem);

    pines_prep_kernel<<<34, 128>>>(cBar, sBar);

    int threads = 224;                       // 7 warps: one wave on 147 SMs
    int blocks  = (pairs + threads - 1) / threads;
    pines_main_kernel<<<blocks, threads, smem>>>(
        (const float4*)inputs, (float2*)out, pairs);
}

// round 7
// speedup vs baseline: 2.0297x; 1.6981x over previous
#include <cuda_runtime.h>
#include <math.h>

// Pines algorithm, degree N=64, B=65536 — single kernel.
// 2 points/thread packed into f32x2; TWO columns (m, m+1) processed
// simultaneously per thread for 2x ILP; rho folded into the Legendre
// recurrence (b_l = rho^l * a_l, MU/r in seed) -> 6 packed ops per (l,m).
// Each block builds its own smem constant tables in fp32 (no prep kernel).

#define N_DEG 64
#define LDIM  65
#define CDIM  67
#define CS_ENTRIES 2145      // sum_{m=0..64} (65-m)
#define NN_ENTRIES 2016      // sum_{m=0..62} (63-m)
#define TPB   224            // 7 warps; one wave of 147 blocks for 32768 pairs

typedef unsigned long long u64;

static __constant__ float c_MU   = 398600441800000.0f;
static __constant__ float c_AREF = 6378136.3f;

// ---------------------------------------------------------------------------
// f32x2 helpers
// ---------------------------------------------------------------------------
__device__ __forceinline__ u64 fma2(u64 a, u64 b, u64 c) {
    u64 d; asm("fma.rn.f32x2 %0, %1, %2, %3;" : "=l"(d) : "l"(a), "l"(b), "l"(c));
    return d;
}
__device__ __forceinline__ u64 mul2(u64 a, u64 b) {
    u64 d; asm("mul.rn.f32x2 %0, %1, %2;" : "=l"(d) : "l"(a), "l"(b));
    return d;
}
__device__ __forceinline__ u64 pack2(float lo, float hi) {
    u64 d; asm("mov.b64 %0, {%1, %2};" : "=l"(d) : "f"(lo), "f"(hi));
    return d;
}
__device__ __forceinline__ void unpack2(u64 v, float& lo, float& hi) {
    asm("mov.b64 {%0, %1}, %2;" : "=f"(lo), "=f"(hi) : "l"(v));
}
__device__ __forceinline__ u64 dupf(float x) {
    unsigned int b = __float_as_uint(x);
    return ((u64)b << 32) | (u64)b;
}
__device__ __forceinline__ float lo32(u64 v) {
    return __uint_as_float((unsigned int)v);
}

// ---------------------------------------------------------------------------
// Main kernel
// ---------------------------------------------------------------------------
__global__ void __launch_bounds__(TPB)
pines_kernel(const float4* __restrict__ inp,
             const float*  __restrict__ cBar,
             const float*  __restrict__ sBar,
             float2*       __restrict__ out, int pairs)
{
    extern __shared__ u64 smraw[];
    ulonglong2* s_cs    = (ulonglong2*)smraw;            // {dup c, dup s}
    ulonglong2* s_nn    = s_cs + CS_ENTRIES;             // {dup n1, dup -n2}
    u64*        s_diag2 = (u64*)(s_nn + NN_ENTRIES);     // 66
    u64*        s_sd2   = s_diag2 + 66;                  // 66

    int tid = threadIdx.x;

    // ---- per-block table build (fp32) ----
    if (tid < 66) {   // diag[l] = cumprod of f_i, computed independently per l
        int l = tid;
        float d = 1.0f;
        for (int i = 1; i <= l; ++i) {
            float kl   = 2.0f;
            float klm1 = (i == 1) ? 1.0f : 2.0f;
            d *= sqrtf((2.0f * i + 1.0f) * kl / (2.0f * i * klm1));
        }
        s_diag2[l] = dupf(d);
    }
    __syncthreads();
    if (tid < 65) {   // sd[m] = sub[m+1] * diag[m+1]
        int m = tid;
        int l = m + 1;
        float kl   = 2.0f;
        float klm1 = (l == 1) ? 1.0f : 2.0f;
        float sub  = sqrtf(2.0f * l * klm1 / kl);
        s_sd2[m] = dupf(sub * lo32(s_diag2[m + 1]));
    }
    for (int i = tid; i < LDIM * LDIM; i += TPB) {
        int l = i / LDIM;
        int m = i % LDIM;
        if (l < m) continue;
        int csBase = 65 * m - (m * (m - 1)) / 2;
        float c = cBar[l * CDIM + m];
        float s = sBar[l * CDIM + m];
        if (i == 0) { c = 0.0f; s = 0.0f; }   // (l=0,m=0) excluded from sum
        ulonglong2 cs; cs.x = dupf(c); cs.y = dupf(s);
        s_cs[csBase + (l - m)] = cs;
        if (l >= m + 2) {
            int nnBase = 63 * m - (m * (m - 1)) / 2;
            float fl = (float)l, fm = (float)m;
            float n1 = sqrtf((2.0f * fl + 1.0f) * (2.0f * fl - 1.0f) /
                             ((fl - fm) * (fl + fm)));
            float n2 = sqrtf((fl + fm - 1.0f) * (2.0f * fl + 1.0f) * (fl - fm - 1.0f) /
                             ((fl + fm) * (fl - fm) * (2.0f * fl - 3.0f)));
            ulonglong2 nn; nn.x = dupf(n1); nn.y = dupf(-n2);
            s_nn[nnBase + (l - m - 2)] = nn;
        }
    }
    __syncthreads();

    int p = blockIdx.x * TPB + tid;
    if (p >= pairs) return;

    float4 v0 = inp[2 * p + 0];
    float4 v1 = inp[2 * p + 1];

    u64 rho2  = pack2(c_AREF / v0.x, c_AREF / v1.x);
    u64 rm    = pack2(c_MU / v0.x,  c_MU / v1.x);     // (MU/r) * rho^m
    u64 s2    = pack2(v0.y,  v1.y);
    u64 t2    = pack2(v0.z,  v1.z);
    u64 nt2   = pack2(-v0.z, -v1.z);
    u64 u2    = pack2(v0.w,  v1.w);
    u64 rhosq = mul2(rho2, rho2);
    u64 urho  = mul2(u2, rho2);

    u64 acc  = rm;                      // MU/r leading (l=0) term
    u64 cre  = pack2(1.0f, 1.0f);       // Re/Im (s+it)^m
    u64 cim  = 0ULL;

    int csBase = 0, nnBase = 0;

    #pragma unroll 1
    for (int m = 0; m < N_DEG; m += 2) {
        // phasor for column B (order m+1)
        u64 creB = fma2(s2, cre, mul2(nt2, cim));
        u64 cimB = fma2(s2, cim, mul2(t2,  cre));
        u64 rmB  = mul2(rm, rho2);      // (MU/r) rho^{m+1}
        u64 rmB2 = mul2(rmB, rho2);     // (MU/r) rho^{m+2}

        // seeds: b_l = (MU/r) rho^l a_l
        u64 bA2 = mul2(rm,   s_diag2[m]);                // colA: l=m
        u64 bA1 = mul2(rmB,  mul2(s_sd2[m],     u2));    // colA: l=m+1
        u64 bB2 = mul2(rmB,  s_diag2[m + 1]);            // colB: l=m+1
        u64 bB1 = mul2(rmB2, mul2(s_sd2[m + 1], u2));    // colB: l=m+2

        const ulonglong2* pcsA = s_cs + csBase;
        const ulonglong2* pnnA = s_nn + nnBase;
        const ulonglong2* pcsB = pcsA + (65 - m);
        const ulonglong2* pnnB = pnnA + (63 - m);

        u64 accCA, accSA, accCB, accSB;
        {
            ulonglong2 cs0 = pcsA[0], cs1 = pcsA[1];
            accCA = mul2(bA2, cs0.x);  accSA = mul2(bA2, cs0.y);
            accCA = fma2(bA1, cs1.x, accCA);  accSA = fma2(bA1, cs1.y, accSA);
        }
        {
            ulonglong2 cs0 = pcsB[0], cs1 = pcsB[1];
            accCB = mul2(bB2, cs0.x);  accSB = mul2(bB2, cs0.y);
            accCB = fma2(bB1, cs1.x, accCB);  accSB = fma2(bB1, cs1.y, accSB);
        }
        pcsA += 2;  pcsB += 2;

        // peel one extra step for column A (it has one more l than B)
        {
            ulonglong2 nn = *pnnA++;
            ulonglong2 cs = *pcsA++;
            u64 t1 = mul2(nn.x, bA1);
            u64 tt = mul2(nn.y, bA2);
            u64 b  = fma2(urho, t1, mul2(rhosq, tt));
            bA2 = bA1;  bA1 = b;
            accCA = fma2(b, cs.x, accCA);
            accSA = fma2(b, cs.y, accSA);
        }

        int nB = 62 - m;   // remaining steps for both columns
        #pragma unroll 2
        for (int k = 0; k < nB; ++k) {
            ulonglong2 nnA = *pnnA++;
            ulonglong2 csA = *pcsA++;
            ulonglong2 nnB_ = *pnnB++;
            ulonglong2 csB = *pcsB++;

            u64 tA1 = mul2(nnA.x, bA1);
            u64 tA2 = mul2(nnA.y, bA2);
            u64 tB1 = mul2(nnB_.x, bB1);
            u64 tB2 = mul2(nnB_.y, bB2);

            u64 bA = fma2(urho, tA1, mul2(rhosq, tA2));
            u64 bB = fma2(urho, tB1, mul2(rhosq, tB2));

            bA2 = bA1;  bA1 = bA;
            bB2 = bB1;  bB1 = bB;

            accCA = fma2(bA, csA.x, accCA);
            accSA = fma2(bA, csA.y, accSA);
            accCB = fma2(bB, csB.x, accCB);
            accSB = fma2(bB, csB.y, accSB);
        }

        // apply phasors once per column
        acc = fma2(cre,  accCA, acc);
        acc = fma2(cim,  accSA, acc);
        acc = fma2(creB, accCB, acc);
        acc = fma2(cimB, accSB, acc);

        // advance phasor and rho power by 2
        cre = fma2(s2, creB, mul2(nt2, cimB));
        cim = fma2(s2, cimB, mul2(t2,  creB));
        rm  = rmB2;

        csBase += (65 - m) + (64 - m);
        nnBase += (63 - m) + (62 - m);
    }

    // tail column m = 64: single l = 64 term
    {
        ulonglong2 cs = s_cs[csBase];      // entry (64,64)
        u64 b = mul2(rm, s_diag2[N_DEG]);
        acc = fma2(cre, mul2(b, cs.x), acc);
        acc = fma2(cim, mul2(b, cs.y), acc);
    }

    float lo, hi;
    unpack2(acc, lo, hi);
    out[p] = make_float2(-lo, -hi);
}

// ---------------------------------------------------------------------------
// Launch — single kernel
// ---------------------------------------------------------------------------
extern "C" void kernel_launch(void* const* d_in, const int* in_sizes, int n_in,
                              void* d_out, int out_size)
{
    const float* inputs = (const float*)d_in[0];  // [B,4] : r,s,t,u
    const float* cBar   = (const float*)d_in[1];  // [67,67]
    const float* sBar   = (const float*)d_in[2];  // [67,67]
    float*       out    = (float*)d_out;          // [B]

    int B     = in_sizes[0] / 4;
    int pairs = B / 2;

    const size_t smem = CS_ENTRIES * sizeof(ulonglong2)
                      + NN_ENTRIES * sizeof(ulonglong2)
                      + 2 * 66 * sizeof(u64);     // 67,632 B
    cudaFuncSetAttribute(pines_kernel,
                         cudaFuncAttributeMaxDynamicSharedMemorySize,
                         (int)smem);

    int blocks = (pairs + TPB - 1) / TPB;         // 147
    pines_kernel<<<blocks, TPB, smem>>>(
        (const float4*)inputs, cBar, sBar, (float2*)out, pairs);
}

// round 8
// speedup vs baseline: 2.2888x; 1.1277x over previous
#include <cuda_runtime.h>
#include <math.h>

// Pines algorithm, degree N=64, B=65536 — single kernel.
// 4 points per thread as TWO independent f32x2 chains sharing table loads;
// the 65 m-columns are split 4 ways across threads (snake-balanced),
// partials combined with shfl_xor. 147 blocks x 448 thr = one wave, 14 warps/SM.

#define N_DEG 64
#define LDIM  65
#define CDIM  67
#define CS_ENTRIES 2145      // sum_{m=0..64} (65-m)
#define NN_ENTRIES 2016      // sum_{m=0..62} (63-m)
#define TPB   448            // 14 warps

typedef unsigned long long u64;

static __constant__ float c_MU   = 398600441800000.0f;
static __constant__ float c_AREF = 6378136.3f;

// ---------------------------------------------------------------------------
// f32x2 helpers
// ---------------------------------------------------------------------------
__device__ __forceinline__ u64 fma2(u64 a, u64 b, u64 c) {
    u64 d; asm("fma.rn.f32x2 %0, %1, %2, %3;" : "=l"(d) : "l"(a), "l"(b), "l"(c));
    return d;
}
__device__ __forceinline__ u64 mul2(u64 a, u64 b) {
    u64 d; asm("mul.rn.f32x2 %0, %1, %2;" : "=l"(d) : "l"(a), "l"(b));
    return d;
}
__device__ __forceinline__ u64 add2(u64 a, u64 b) {
    u64 d; asm("add.rn.f32x2 %0, %1, %2;" : "=l"(d) : "l"(a), "l"(b));
    return d;
}
__device__ __forceinline__ u64 pack2(float lo, float hi) {
    u64 d; asm("mov.b64 %0, {%1, %2};" : "=l"(d) : "f"(lo), "f"(hi));
    return d;
}
__device__ __forceinline__ void unpack2(u64 v, float& lo, float& hi) {
    asm("mov.b64 {%0, %1}, %2;" : "=f"(lo), "=f"(hi) : "l"(v));
}
__device__ __forceinline__ u64 dupf(float x) {
    unsigned int b = __float_as_uint(x);
    return ((u64)b << 32) | (u64)b;
}
__device__ __forceinline__ float lo32(u64 v) {
    return __uint_as_float((unsigned int)v);
}
__device__ __forceinline__ u64 sel4(int j, u64 a0, u64 a1, u64 a2, u64 a3) {
    return j == 0 ? a0 : (j == 1 ? a1 : (j == 2 ? a2 : a3));
}

// Per-chain state (one f32x2 chain = 2 points)
struct Chain {
    u64 rho, urho, rhosq, u2;      // invariants
    u64 rm;                        // (MU/r) * rho^m at current column m
    u64 acc;                       // potential accumulator
    u64 cre, cim;                  // (s+it)^m at current column m
    u64 pAr, pAi, npAi;            // jump factor A = (s+it)^(7-2j), neg imag
    u64 pBr, pBi, npBi;            // jump factor B = (s+it)^(1+2j)
    u64 rA, rB;                    // rho^(7-2j), rho^(1+2j)
};

__device__ __forceinline__ void chain_init(Chain& C, float4 v0, float4 v1, int j)
{
    float r0 = v0.x, r1 = v1.x;
    C.rho   = pack2(c_AREF / r0, c_AREF / r1);
    u64 mu  = pack2(c_MU / r0, c_MU / r1);
    u64 s2  = pack2(v0.y, v1.y);
    u64 t2  = pack2(v0.z, v1.z);
    u64 nt2 = pack2(-v0.z, -v1.z);
    C.u2    = pack2(v0.w, v1.w);
    C.rhosq = mul2(C.rho, C.rho);
    C.urho  = mul2(C.u2, C.rho);

    // rho powers 1..7
    u64 r1p = C.rho;
    u64 r2p = C.rhosq;
    u64 r3p = mul2(r2p, r1p);
    u64 r5p = mul2(r3p, r2p);
    u64 r7p = mul2(r5p, r2p);
    // phasor powers (s+it)^1..7
    u64 p1r = s2, p1i = t2;
    u64 p2r = fma2(s2, p1r, mul2(nt2, p1i));
    u64 p2i = fma2(s2, p1i, mul2(t2, p1r));
    u64 p3r = fma2(s2, p2r, mul2(nt2, p2i));
    u64 p3i = fma2(s2, p2i, mul2(t2, p2r));
    u64 p5r = fma2(p2r, p3r, mul2(mul2(p2i, p3i), pack2(-1.0f, -1.0f)));
    u64 p5i = fma2(p2r, p3i, mul2(p2i, p3r));
    u64 p7r = fma2(p2r, p5r, mul2(mul2(p2i, p5i), pack2(-1.0f, -1.0f)));
    u64 p7i = fma2(p2r, p5i, mul2(p2i, p5r));

    u64 one2 = pack2(1.0f, 1.0f);
    // start at column m = j
    C.cre = sel4(j, one2, p1r, p2r, p3r);
    C.cim = sel4(j, 0ULL, p1i, p2i, p3i);
    C.rm  = mul2(mu, sel4(j, one2, r1p, r2p, r3p));
    // jumps: A = 7-2j, B = 1+2j
    C.pAr = sel4(j, p7r, p5r, p3r, p1r);
    C.pAi = sel4(j, p7i, p5i, p3i, p1i);
    C.pBr = sel4(j, p1r, p3r, p5r, p7r);
    C.pBi = sel4(j, p1i, p3i, p5i, p7i);
    u64 neg1 = pack2(-1.0f, -1.0f);
    C.npAi = mul2(C.pAi, neg1);
    C.npBi = mul2(C.pBi, neg1);
    C.rA  = sel4(j, r7p, r5p, r3p, r1p);
    C.rB  = sel4(j, r1p, r3p, r5p, r7p);

    C.acc = (j == 0) ? mu : 0ULL;   // MU/r leading term, added once
}

__device__ __forceinline__ void chain_jumpA(Chain& C) {
    u64 nr = fma2(C.cre, C.pAr, mul2(C.cim, C.npAi));
    u64 ni = fma2(C.cim, C.pAr, mul2(C.cre, C.pAi));
    C.cre = nr; C.cim = ni;
    C.rm = mul2(C.rm, C.rA);
}
__device__ __forceinline__ void chain_jumpB(Chain& C) {
    u64 nr = fma2(C.cre, C.pBr, mul2(C.cim, C.npBi));
    u64 ni = fma2(C.cim, C.pBr, mul2(C.cre, C.pBi));
    C.cre = nr; C.cim = ni;
    C.rm = mul2(C.rm, C.rB);
}

// ---------------------------------------------------------------------------
// Main kernel
// ---------------------------------------------------------------------------
__global__ void __launch_bounds__(TPB)
pines_kernel(const float4* __restrict__ inp,
             const float*  __restrict__ cBar,
             const float*  __restrict__ sBar,
             float2*       __restrict__ out, int quads)
{
    extern __shared__ u64 smraw[];
    ulonglong2* s_cs    = (ulonglong2*)smraw;            // {dup c, dup s}
    ulonglong2* s_nn    = s_cs + CS_ENTRIES;             // {dup n1, dup -n2}
    u64*        s_diag2 = (u64*)(s_nn + NN_ENTRIES);     // 66
    u64*        s_sd2   = s_diag2 + 66;                  // 65

    int tid = threadIdx.x;

    // ---- per-block table build (fp32) ----
    if (tid < 66) {
        int l = tid;
        float d = 1.0f;
        for (int i = 1; i <= l; ++i) {
            float kl   = 2.0f;
            float klm1 = (i == 1) ? 1.0f : 2.0f;
            d *= sqrtf((2.0f * i + 1.0f) * kl / (2.0f * i * klm1));
        }
        s_diag2[l] = dupf(d);
    }
    __syncthreads();
    if (tid < 65) {
        int m = tid;
        int l = m + 1;
        float kl   = 2.0f;
        float klm1 = (l == 1) ? 1.0f : 2.0f;
        float sub  = sqrtf(2.0f * l * klm1 / kl);
        s_sd2[m] = dupf(sub * lo32(s_diag2[m + 1]));
    }
    for (int i = tid; i < LDIM * LDIM; i += TPB) {
        int l = i / LDIM;
        int m = i % LDIM;
        if (l < m) continue;
        int csBase = 65 * m - (m * (m - 1)) / 2;
        float c = cBar[l * CDIM + m];
        float s = sBar[l * CDIM + m];
        if (i == 0) { c = 0.0f; s = 0.0f; }   // (0,0) term excluded (MU/r instead)
        ulonglong2 cs; cs.x = dupf(c); cs.y = dupf(s);
        s_cs[csBase + (l - m)] = cs;
        if (l >= m + 2) {
            int nnBase = 63 * m - (m * (m - 1)) / 2;
            float fl = (float)l, fm = (float)m;
            float n1 = sqrtf((2.0f * fl + 1.0f) * (2.0f * fl - 1.0f) /
                             ((fl - fm) * (fl + fm)));
            float n2 = sqrtf((fl + fm - 1.0f) * (2.0f * fl + 1.0f) * (fl - fm - 1.0f) /
                             ((fl + fm) * (fl - fm) * (2.0f * fl - 3.0f)));
            ulonglong2 nn; nn.x = dupf(n1); nn.y = dupf(-n2);
            s_nn[nnBase + (l - m - 2)] = nn;
        }
    }
    __syncthreads();

    int g = blockIdx.x * TPB + tid;
    int j = g & 3;          // column-set id within the 4-thread team
    int q = g >> 2;         // point-quad index
    bool valid = (q < quads);
    if (!valid) q = quads - 1;

    const float4* pv = inp + 4 * q;
    float4 v0 = pv[0], v1 = pv[1], v2 = pv[2], v3 = pv[3];

    Chain X, Y;
    chain_init(X, v0, v1, j);
    chain_init(Y, v2, v3, j);

    // snake over columns: for b in 0..7, process m=8b+j then m=8b+7-j
    #pragma unroll 1
    for (int b = 0; b < 8; ++b) {
        #pragma unroll
        for (int half = 0; half < 2; ++half) {
            int m = (half == 0) ? (8 * b + j) : (8 * b + 7 - j);

            int csb = 65 * m - (m * (m - 1)) / 2;
            int nnb = 63 * m - (m * (m - 1)) / 2;
            const ulonglong2* pcs = s_cs + csb;
            const ulonglong2* pnn = s_nn + nnb;

            u64 dg = s_diag2[m];
            u64 sd = s_sd2[m];

            // seeds: b_l = (MU/r) rho^l a_l for l = m, m+1
            u64 bX2 = mul2(X.rm, dg);
            u64 bY2 = mul2(Y.rm, dg);
            u64 bX1 = mul2(mul2(X.rm, X.rho), mul2(sd, X.u2));
            u64 bY1 = mul2(mul2(Y.rm, Y.rho), mul2(sd, Y.u2));

            ulonglong2 cs0 = pcs[0], cs1 = pcs[1];
            u64 aCX = mul2(bX2, cs0.x), aSX = mul2(bX2, cs0.y);
            u64 aCY = mul2(bY2, cs0.x), aSY = mul2(bY2, cs0.y);
            aCX = fma2(bX1, cs1.x, aCX);  aSX = fma2(bX1, cs1.y, aSX);
            aCY = fma2(bY1, cs1.x, aCY);  aSY = fma2(bY1, cs1.y, aSY);
            pcs += 2;

            int n = 63 - m;
            #pragma unroll 2
            for (int k = 0; k < n; ++k) {
                ulonglong2 nn = pnn[k];
                ulonglong2 cs = pcs[k];

                u64 tX1 = mul2(nn.x, bX1);
                u64 tX2 = mul2(nn.y, bX2);
                u64 tY1 = mul2(nn.x, bY1);
                u64 tY2 = mul2(nn.y, bY2);

                u64 bX = fma2(X.urho, tX1, mul2(X.rhosq, tX2));
                u64 bY = fma2(Y.urho, tY1, mul2(Y.rhosq, tY2));

                aCX = fma2(bX, cs.x, aCX);  aSX = fma2(bX, cs.y, aSX);
                aCY = fma2(bY, cs.x, aCY);  aSY = fma2(bY, cs.y, aSY);

                bX2 = bX1; bX1 = bX;
                bY2 = bY1; bY1 = bY;
            }

            // apply phasor for this column
            X.acc = fma2(X.cre, aCX, X.acc);
            X.acc = fma2(X.cim, aSX, X.acc);
            Y.acc = fma2(Y.cre, aCY, Y.acc);
            Y.acc = fma2(Y.cim, aSY, Y.acc);

            // jump to this thread's next column
            if (half == 0) { chain_jumpA(X); chain_jumpA(Y); }
            else           { chain_jumpB(X); chain_jumpB(Y); }
        }
    }

    // tail column m = 64 (single l=64 term) — lands on thread j==0,
    // whose phasor/rm are now exactly at m=64.
    if (j == 0) {
        ulonglong2 cs = s_cs[CS_ENTRIES - 1];
        u64 dg = s_diag2[N_DEG];
        u64 bX = mul2(X.rm, dg);
        u64 bY = mul2(Y.rm, dg);
        X.acc = fma2(X.cre, mul2(bX, cs.x), X.acc);
        X.acc = fma2(X.cim, mul2(bX, cs.y), X.acc);
        Y.acc = fma2(Y.cre, mul2(bY, cs.x), Y.acc);
        Y.acc = fma2(Y.cim, mul2(bY, cs.y), Y.acc);
    }

    // combine the 4 column-set partials within each quad of lanes
    u64 aX = X.acc, aY = Y.acc;
    aX = add2(aX, __shfl_xor_sync(0xffffffffu, aX, 1));
    aX = add2(aX, __shfl_xor_sync(0xffffffffu, aX, 2));
    aY = add2(aY, __shfl_xor_sync(0xffffffffu, aY, 1));
    aY = add2(aY, __shfl_xor_sync(0xffffffffu, aY, 2));

    if (valid && j == 0) {
        float lx, hx, ly, hy;
        unpack2(aX, lx, hx);
        unpack2(aY, ly, hy);
        out[2 * q + 0] = make_float2(-lx, -hx);
        out[2 * q + 1] = make_float2(-ly, -hy);
    }
}

// ---------------------------------------------------------------------------
// Launch — single kernel
// ---------------------------------------------------------------------------
extern "C" void kernel_launch(void* const* d_in, const int* in_sizes, int n_in,
                              void* d_out, int out_size)
{
    const float* inputs = (const float*)d_in[0];  // [B,4] : r,s,t,u
    const float* cBar   = (const float*)d_in[1];  // [67,67]
    const float* sBar   = (const float*)d_in[2];  // [67,67]
    float*       out    = (float*)d_out;          // [B]

    int B     = in_sizes[0] / 4;
    int quads = B / 4;                            // 16384

    const size_t smem = CS_ENTRIES * sizeof(ulonglong2)
                      + NN_ENTRIES * sizeof(ulonglong2)
                      + (66 + 65) * sizeof(u64);
    cudaFuncSetAttribute(pines_kernel,
                         cudaFuncAttributeMaxDynamicSharedMemorySize,
                         (int)smem);

    int threads_total = quads * 4;                // 65536
    int blocks = (threads_total + TPB - 1) / TPB; // 147
    pines_kernel<<<blocks, TPB, smem>>>(
        (const float4*)inputs, cBar, sBar, (float2*)out, quads);
}

// round 9
// speedup vs baseline: 2.3110x; 1.0097x over previous
#include <cuda_runtime.h>
#include <math.h>

// Pines algorithm, degree N=64, B=65536 — single kernel.
// 8 points/thread as FOUR independent f32x2 chains sharing every table load
// (fixes the R8 LDS-bandwidth bind). 65 m-columns split 4 ways across the
// threads of each lane-quad with STRIDE-4 assignment (m = 4c + j), so the
// per-thread column jump is a single shared (s+it)^4 / rho^4 factor.
// Partials combined with shfl_xor. 147 blocks x 224 thr, one wave.

#define N_DEG 64
#define LDIM  65
#define CDIM  67
#define CS_ENTRIES 2145      // sum_{m=0..64} (65-m)
#define NN_ENTRIES 2016      // sum_{m=0..62} (63-m)
#define TPB   224            // 7 warps

typedef unsigned long long u64;

static __constant__ float c_MU   = 398600441800000.0f;
static __constant__ float c_AREF = 6378136.3f;

// ---------------------------------------------------------------------------
// f32x2 helpers
// ---------------------------------------------------------------------------
__device__ __forceinline__ u64 fma2(u64 a, u64 b, u64 c) {
    u64 d; asm("fma.rn.f32x2 %0, %1, %2, %3;" : "=l"(d) : "l"(a), "l"(b), "l"(c));
    return d;
}
__device__ __forceinline__ u64 mul2(u64 a, u64 b) {
    u64 d; asm("mul.rn.f32x2 %0, %1, %2;" : "=l"(d) : "l"(a), "l"(b));
    return d;
}
__device__ __forceinline__ u64 add2(u64 a, u64 b) {
    u64 d; asm("add.rn.f32x2 %0, %1, %2;" : "=l"(d) : "l"(a), "l"(b));
    return d;
}
__device__ __forceinline__ u64 pack2(float lo, float hi) {
    u64 d; asm("mov.b64 %0, {%1, %2};" : "=l"(d) : "f"(lo), "f"(hi));
    return d;
}
__device__ __forceinline__ void unpack2(u64 v, float& lo, float& hi) {
    asm("mov.b64 {%0, %1}, %2;" : "=f"(lo), "=f"(hi) : "l"(v));
}
__device__ __forceinline__ u64 dupf(float x) {
    unsigned int b = __float_as_uint(x);
    return ((u64)b << 32) | (u64)b;
}
__device__ __forceinline__ float lo32(u64 v) {
    return __uint_as_float((unsigned int)v);
}
__device__ __forceinline__ u64 sel4(int j, u64 a0, u64 a1, u64 a2, u64 a3) {
    return j == 0 ? a0 : (j == 1 ? a1 : (j == 2 ? a2 : a3));
}

// One f32x2 chain = 2 points. Stride-4 column walk state.
struct Chain {
    u64 rho, urho, rhosq, u2;      // invariants
    u64 rm;                        // (MU/r) * rho^m at current column m
    u64 acc;                       // potential accumulator
    u64 cre, cim;                  // (s+it)^m at current column m
    u64 p4r, p4i, np4i, rho4;      // column jump: (s+it)^4, rho^4
};

__device__ __forceinline__ void chain_init(Chain& C, float4 v0, float4 v1, int j)
{
    float r0 = v0.x, r1 = v1.x;
    C.rho   = pack2(c_AREF / r0, c_AREF / r1);
    u64 mu  = pack2(c_MU / r0, c_MU / r1);
    u64 s2  = pack2(v0.y, v1.y);
    u64 t2  = pack2(v0.z, v1.z);
    u64 nt2 = pack2(-v0.z, -v1.z);
    C.u2    = pack2(v0.w, v1.w);
    C.rhosq = mul2(C.rho, C.rho);
    C.urho  = mul2(C.u2, C.rho);
    C.rho4  = mul2(C.rhosq, C.rhosq);

    u64 neg1 = pack2(-1.0f, -1.0f);
    // (s+it)^2
    u64 p2r = fma2(s2, s2, mul2(nt2, t2));
    u64 st  = mul2(s2, t2);
    u64 p2i = add2(st, st);
    // (s+it)^3 (for j==3 start)
    u64 p3r = fma2(p2r, s2, mul2(p2i, nt2));
    u64 p3i = fma2(p2i, s2, mul2(p2r, t2));
    // (s+it)^4
    u64 pi2 = mul2(p2i, p2i);
    C.p4r   = fma2(p2r, p2r, mul2(pi2, neg1));
    u64 rr  = mul2(p2r, p2i);
    C.p4i   = add2(rr, rr);
    C.np4i  = mul2(C.p4i, neg1);

    u64 one2 = pack2(1.0f, 1.0f);
    u64 r3p  = mul2(C.rhosq, C.rho);
    C.cre = sel4(j, one2, s2,    p2r, p3r);
    C.cim = sel4(j, 0ULL, t2,    p2i, p3i);
    C.rm  = mul2(mu, sel4(j, one2, C.rho, C.rhosq, r3p));

    C.acc = (j == 0) ? mu : 0ULL;   // MU/r leading term, added once
}

__device__ __forceinline__ void chain_jump(Chain& C) {
    u64 nr = fma2(C.cre, C.p4r, mul2(C.cim, C.np4i));
    u64 ni = fma2(C.cim, C.p4r, mul2(C.cre, C.p4i));
    C.cre = nr; C.cim = ni;
    C.rm  = mul2(C.rm, C.rho4);
}

// ---------------------------------------------------------------------------
// Main kernel
// ---------------------------------------------------------------------------
__global__ void __launch_bounds__(TPB)
pines_kernel(const float4* __restrict__ inp,
             const float*  __restrict__ cBar,
             const float*  __restrict__ sBar,
             float2*       __restrict__ out, int quads)
{
    extern __shared__ u64 smraw[];
    ulonglong2* s_cs    = (ulonglong2*)smraw;            // {dup c, dup s}
    ulonglong2* s_nn    = s_cs + CS_ENTRIES;             // {dup n1, dup -n2}
    u64*        s_diag2 = (u64*)(s_nn + NN_ENTRIES);     // 66
    u64*        s_sd2   = s_diag2 + 66;                  // 65

    int tid = threadIdx.x;

    // ---- per-block table build (fp32) ----
    if (tid < 66) {
        int l = tid;
        float d = 1.0f;
        for (int i = 1; i <= l; ++i) {
            float kl   = 2.0f;
            float klm1 = (i == 1) ? 1.0f : 2.0f;
            d *= sqrtf((2.0f * i + 1.0f) * kl / (2.0f * i * klm1));
        }
        s_diag2[l] = dupf(d);
    }
    __syncthreads();
    if (tid < 65) {
        int m = tid;
        int l = m + 1;
        float kl   = 2.0f;
        float klm1 = (l == 1) ? 1.0f : 2.0f;
        float sub  = sqrtf(2.0f * l * klm1 / kl);
        s_sd2[m] = dupf(sub * lo32(s_diag2[m + 1]));
    }
    for (int i = tid; i < LDIM * LDIM; i += TPB) {
        int l = i / LDIM;
        int m = i % LDIM;
        if (l < m) continue;
        int csBase = 65 * m - (m * (m - 1)) / 2;
        float c = cBar[l * CDIM + m];
        float s = sBar[l * CDIM + m];
        if (i == 0) { c = 0.0f; s = 0.0f; }   // (0,0) term excluded (MU/r instead)
        ulonglong2 cs; cs.x = dupf(c); cs.y = dupf(s);
        s_cs[csBase + (l - m)] = cs;
        if (l >= m + 2) {
            int nnBase = 63 * m - (m * (m - 1)) / 2;
            float fl = (float)l, fm = (float)m;
            float n1 = sqrtf((2.0f * fl + 1.0f) * (2.0f * fl - 1.0f) /
                             ((fl - fm) * (fl + fm)));
            float n2 = sqrtf((fl + fm - 1.0f) * (2.0f * fl + 1.0f) * (fl - fm - 1.0f) /
                             ((fl + fm) * (fl - fm) * (2.0f * fl - 3.0f)));
            ulonglong2 nn; nn.x = dupf(n1); nn.y = dupf(-n2);
            s_nn[nnBase + (l - m - 2)] = nn;
        }
    }
    __syncthreads();

    int g = blockIdx.x * TPB + tid;
    int j = g & 3;          // column-set id within the 4-lane team
    int q = g >> 2;         // point-octet index
    bool valid = (q < quads);
    if (!valid) q = quads - 1;

    const float4* pv = inp + 8 * q;

    Chain C[4];
    #pragma unroll
    for (int i = 0; i < 4; ++i)
        chain_init(C[i], pv[2 * i], pv[2 * i + 1], j);

    // stride-4 column walk: m = 4c + j, c = 0..15
    #pragma unroll 1
    for (int cidx = 0; cidx < 16; ++cidx) {
        int m = 4 * cidx + j;

        int csb = 65 * m - (m * (m - 1)) / 2;
        int nnb = 63 * m - (m * (m - 1)) / 2;
        const ulonglong2* pcs = s_cs + csb;
        const ulonglong2* pnn = s_nn + nnb;

        u64 dg = s_diag2[m];
        u64 sd = s_sd2[m];

        u64 b1[4], b2[4], aC[4], aS[4];
        ulonglong2 cs0 = pcs[0], cs1 = pcs[1];
        #pragma unroll
        for (int i = 0; i < 4; ++i) {
            // seeds: b_l = (MU/r) rho^l a_l for l = m, m+1
            b2[i] = mul2(C[i].rm, dg);
            b1[i] = mul2(mul2(C[i].rm, C[i].rho), mul2(sd, C[i].u2));
            aC[i] = mul2(b2[i], cs0.x);
            aS[i] = mul2(b2[i], cs0.y);
            aC[i] = fma2(b1[i], cs1.x, aC[i]);
            aS[i] = fma2(b1[i], cs1.y, aS[i]);
        }
        pcs += 2;

        int n = 63 - m;
        #pragma unroll 2
        for (int k = 0; k < n; ++k) {
            ulonglong2 nn = pnn[k];
            ulonglong2 cs = pcs[k];
            #pragma unroll
            for (int i = 0; i < 4; ++i) {
                u64 t1 = mul2(nn.x, b1[i]);
                u64 t2 = mul2(nn.y, b2[i]);
                u64 b  = fma2(C[i].urho, t1, mul2(C[i].rhosq, t2));
                aC[i] = fma2(b, cs.x, aC[i]);
                aS[i] = fma2(b, cs.y, aS[i]);
                b2[i] = b1[i];
                b1[i] = b;
            }
        }

        #pragma unroll
        for (int i = 0; i < 4; ++i) {
            C[i].acc = fma2(C[i].cre, aC[i], C[i].acc);
            C[i].acc = fma2(C[i].cim, aS[i], C[i].acc);
            chain_jump(C[i]);
        }
    }

    // tail column m = 64 (single l=64 term) — j==0 phasor/rm now at m=64
    if (j == 0) {
        ulonglong2 cs = s_cs[CS_ENTRIES - 1];
        u64 dg = s_diag2[N_DEG];
        #pragma unroll
        for (int i = 0; i < 4; ++i) {
            u64 b = mul2(C[i].rm, dg);
            C[i].acc = fma2(C[i].cre, mul2(b, cs.x), C[i].acc);
            C[i].acc = fma2(C[i].cim, mul2(b, cs.y), C[i].acc);
        }
    }

    // combine the 4 column-set partials within each lane-quad
    #pragma unroll
    for (int i = 0; i < 4; ++i) {
        u64 a = C[i].acc;
        a = add2(a, __shfl_xor_sync(0xffffffffu, a, 1));
        a = add2(a, __shfl_xor_sync(0xffffffffu, a, 2));
        C[i].acc = a;
    }

    if (valid && j == 0) {
        #pragma unroll
        for (int i = 0; i < 4; ++i) {
            float lo, hi;
            unpack2(C[i].acc, lo, hi);
            out[4 * q + i] = make_float2(-lo, -hi);
        }
    }
}

// ---------------------------------------------------------------------------
// Launch — single kernel
// ---------------------------------------------------------------------------
extern "C" void kernel_launch(void* const* d_in, const int* in_sizes, int n_in,
                              void* d_out, int out_size)
{
    const float* inputs = (const float*)d_in[0];  // [B,4] : r,s,t,u
    const float* cBar   = (const float*)d_in[1];  // [67,67]
    const float* sBar   = (const float*)d_in[2];  // [67,67]
    float*       out    = (float*)d_out;          // [B]

    int B     = in_sizes[0] / 4;
    int quads = B / 8;                            // 8192 point-octets

    const size_t smem = CS_ENTRIES * sizeof(ulonglong2)
                      + NN_ENTRIES * sizeof(ulonglong2)
                      + (66 + 65) * sizeof(u64);
    cudaFuncSetAttribute(pines_kernel,
                         cudaFuncAttributeMaxDynamicSharedMemorySize,
                         (int)smem);

    int threads_total = quads * 4;                // 32768
    int blocks = (threads_total + TPB - 1) / TPB; // 147
    pines_kernel<<<blocks, TPB, smem>>>(
        (const float4*)inputs, cBar, sBar, (float2*)out, quads);
}

// round 10
// speedup vs baseline: 2.6496x; 1.1466x over previous
#include <cuda_runtime.h>
#include <math.h>

// Pines algorithm, degree N=64, B=65536 — single kernel, one wave.
// 8 points/thread = FOUR independent f32x2 chains sharing every table load.
// 65 m-columns split EIGHT ways across lane-octets (m = 8c + j, j = lane&7)
// -> 65536 threads = 14 warps/SM (fixes the R9 latency bind) while keeping
// 4-chain ILP. Table is j-interleaved (256B per (c,k): 8x16B nn | 8x16B cs)
// so every LDS.128 is 128B-contiguous across the octet: 1 wavefront, no
// conflicts, uniform (padded) trip counts -> zero divergence.

#define N_DEG 64
#define CDIM  67
#define TPB   448
#define NCH   4

typedef unsigned long long u64;

static __constant__ float c_MU   = 398600441800000.0f;
static __constant__ float c_AREF = 6378136.3f;

// main table: 280 (c,k)-records of 256B. offs(c) = records before block c.
#define MAIN_BYTES 71680
#define SEED_OFF   71680             // 64 x 48B: {dg,sd}{c0,s0}{c1,s1}
#define TAIL_OFF   (SEED_OFF + 3072) // {c64d, s64d, dg64d}
#define DIAG_OFF   (TAIL_OFF + 32)   // 66 floats scratch
#define SMEM_BYTES (DIAG_OFF + 66 * 4)

__device__ __forceinline__ int offs_c(int c) { return c * (67 - 4 * c); }

// ---------------------------------------------------------------------------
// f32x2 helpers
// ---------------------------------------------------------------------------
__device__ __forceinline__ u64 fma2(u64 a, u64 b, u64 c) {
    u64 d; asm("fma.rn.f32x2 %0, %1, %2, %3;" : "=l"(d) : "l"(a), "l"(b), "l"(c));
    return d;
}
__device__ __forceinline__ u64 mul2(u64 a, u64 b) {
    u64 d; asm("mul.rn.f32x2 %0, %1, %2;" : "=l"(d) : "l"(a), "l"(b));
    return d;
}
__device__ __forceinline__ u64 add2(u64 a, u64 b) {
    u64 d; asm("add.rn.f32x2 %0, %1, %2;" : "=l"(d) : "l"(a), "l"(b));
    return d;
}
__device__ __forceinline__ u64 pack2(float lo, float hi) {
    u64 d; asm("mov.b64 %0, {%1, %2};" : "=l"(d) : "f"(lo), "f"(hi));
    return d;
}
__device__ __forceinline__ void unpack2(u64 v, float& lo, float& hi) {
    asm("mov.b64 {%0, %1}, %2;" : "=f"(lo), "=f"(hi) : "l"(v));
}
__device__ __forceinline__ u64 dupf(float x) {
    unsigned int b = __float_as_uint(x);
    return ((u64)b << 32) | (u64)b;
}

// ---------------------------------------------------------------------------
__global__ void __launch_bounds__(TPB)
pines_kernel(const float4* __restrict__ inp,
             const float*  __restrict__ cBar,
             const float*  __restrict__ sBar,
             float2*       __restrict__ out, int octs)
{
    extern __shared__ char smem[];
    float* s_diag = (float*)(smem + DIAG_OFF);

    int tid = threadIdx.x;

    // ---- diag cumprod (independent per l) ----
    if (tid < 66) {
        int l = tid;
        float d = 1.0f;
        for (int i = 1; i <= l; ++i) {
            float kl   = 2.0f;
            float klm1 = (i == 1) ? 1.0f : 2.0f;
            d *= sqrtf((2.0f * i + 1.0f) * kl / (2.0f * i * klm1));
        }
        s_diag[l] = d;
    }
    __syncthreads();

    // ---- seed records: (c,j) -> {dg,sd},{c0,s0},{c1,s1} ----
    if (tid < 64) {
        int c = tid >> 3, j = tid & 7;
        int m = 8 * c + j;
        int l1 = m + 1;
        float kl   = 2.0f;
        float klm1 = (l1 == 1) ? 1.0f : 2.0f;
        float sub  = sqrtf(2.0f * l1 * klm1 / kl);
        float dg = s_diag[m];
        float sd = sub * s_diag[m + 1];
        float c0 = cBar[m * CDIM + m];
        float s0 = sBar[m * CDIM + m];
        if (m == 0) { c0 = 0.0f; s0 = 0.0f; }       // (0,0) term excluded
        float c1 = cBar[(m + 1) * CDIM + m];
        float s1 = sBar[(m + 1) * CDIM + m];
        ulonglong2* sp = (ulonglong2*)(smem + SEED_OFF + tid * 48);
        sp[0] = make_ulonglong2(dupf(dg), dupf(sd));
        sp[1] = make_ulonglong2(dupf(c0), dupf(s0));
        sp[2] = make_ulonglong2(dupf(c1), dupf(s1));
    }
    if (tid == TPB - 1) {   // tail record for m = 64
        u64* tp = (u64*)(smem + TAIL_OFF);
        tp[0] = dupf(cBar[64 * CDIM + 64]);
        tp[1] = dupf(sBar[64 * CDIM + 64]);
        tp[2] = dupf(s_diag[N_DEG]);
    }

    // ---- main table: 280 records x 8 j-slots ----
    for (int t = tid; t < 280 * 8; t += TPB) {
        int e = t >> 3, j = t & 7;
        int c = 0;
        while (c < 7 && e >= offs_c(c + 1)) ++c;
        int k = e - offs_c(c);
        int m = 8 * c + j;
        int l = m + 2 + k;
        float n1 = 0.0f, n2n = 0.0f, cc = 0.0f, ss = 0.0f;
        if (l <= N_DEG) {
            float fl = (float)l, fm = (float)m;
            n1  = sqrtf((2.0f * fl + 1.0f) * (2.0f * fl - 1.0f) /
                        ((fl - fm) * (fl + fm)));
            n2n = -sqrtf((fl + fm - 1.0f) * (2.0f * fl + 1.0f) * (fl - fm - 1.0f) /
                         ((fl + fm) * (fl - fm) * (2.0f * fl - 3.0f)));
            cc = cBar[l * CDIM + m];
            ss = sBar[l * CDIM + m];
        }
        char* rec = smem + e * 256;
        *(ulonglong2*)(rec + j * 16)       = make_ulonglong2(dupf(n1), dupf(n2n));
        *(ulonglong2*)(rec + 128 + j * 16) = make_ulonglong2(dupf(cc), dupf(ss));
    }
    __syncthreads();

    int g = blockIdx.x * TPB + tid;
    int j = g & 7;          // column-set id within the lane-octet
    int q = g >> 3;         // point-octet index
    bool valid = (q < octs);
    if (!valid) q = octs - 1;

    const float4* pv = inp + 8 * q;

    // ---- chain state (4 chains = 8 points) ----
    u64 urho[NCH], rhosq[NCH], rho8[NCH], rm[NCH], acc[NCH];
    u64 cre[NCH], cim[NCH], p8r[NCH], p8i[NCH];
    u64 negone = pack2(-1.0f, -1.0f);

    #pragma unroll
    for (int i = 0; i < NCH; ++i) {
        float4 v0 = pv[2 * i], v1 = pv[2 * i + 1];
        u64 rho = pack2(c_AREF / v0.x, c_AREF / v1.x);
        u64 mu  = pack2(c_MU  / v0.x, c_MU  / v1.x);
        u64 s2  = pack2(v0.y, v1.y);
        u64 t2  = pack2(v0.z, v1.z);
        u64 nt2 = mul2(t2, negone);
        u64 uu  = pack2(v0.w, v1.w);
        urho[i]  = mul2(uu, rho);
        rhosq[i] = mul2(rho, rho);
        u64 rho4 = mul2(rhosq[i], rhosq[i]);
        rho8[i]  = mul2(rho4, rho4);
        // (s+it)^8 by repeated squaring
        u64 p2r = fma2(s2, s2, mul2(nt2, t2));
        u64 st  = mul2(s2, t2);
        u64 p2i = add2(st, st);
        u64 p4r = fma2(p2r, p2r, mul2(mul2(p2i, p2i), negone));
        u64 rr  = mul2(p2r, p2i);
        u64 p4i = add2(rr, rr);
        p8r[i]  = fma2(p4r, p4r, mul2(mul2(p4i, p4i), negone));
        u64 qq  = mul2(p4r, p4i);
        p8i[i]  = add2(qq, qq);
        // start at column m = j : (s+it)^j, mu*rho^j
        u64 cr = pack2(1.0f, 1.0f), ci = 0ULL, r = mu;
        for (int it = 0; it < j; ++it) {
            u64 nr = fma2(s2, cr, mul2(nt2, ci));
            u64 ni = fma2(s2, ci, mul2(t2, cr));
            cr = nr; ci = ni;
            r = mul2(r, rho);
        }
        cre[i] = cr; cim[i] = ci; rm[i] = r;
        acc[i] = (j == 0) ? mu : 0ULL;     // MU/r leading term, once
    }

    // ---- column walk: m = 8c + j, c = 0..7 ----
    #pragma unroll 1
    for (int c = 0; c < 8; ++c) {
        const ulonglong2* sp =
            (const ulonglong2*)(smem + SEED_OFF + (c * 8 + j) * 48);
        ulonglong2 dgsd = sp[0], cs0 = sp[1], cs1 = sp[2];

        u64 b1[NCH], b2[NCH], aC[NCH], aS[NCH];
        #pragma unroll
        for (int i = 0; i < NCH; ++i) {
            b2[i] = mul2(rm[i], dgsd.x);                     // l = m
            b1[i] = mul2(mul2(rm[i], urho[i]), dgsd.y);      // l = m+1
            aC[i] = mul2(b2[i], cs0.x);
            aS[i] = mul2(b2[i], cs0.y);
            aC[i] = fma2(b1[i], cs1.x, aC[i]);
            aS[i] = fma2(b1[i], cs1.y, aS[i]);
        }

        const char* p = smem + offs_c(c) * 256 + j * 16;
        int n = 63 - 8 * c;                                  // uniform (padded)
        #pragma unroll 2
        for (int k = 0; k < n; ++k) {
            ulonglong2 nn = *(const ulonglong2*)(p);
            ulonglong2 cs = *(const ulonglong2*)(p + 128);
            p += 256;
            #pragma unroll
            for (int i = 0; i < NCH; ++i) {
                u64 t1 = mul2(nn.x, b1[i]);
                u64 t2 = mul2(nn.y, b2[i]);
                u64 b  = fma2(urho[i], t1, mul2(rhosq[i], t2));
                aC[i] = fma2(b, cs.x, aC[i]);
                aS[i] = fma2(b, cs.y, aS[i]);
                b2[i] = b1[i];
                b1[i] = b;
            }
        }

        #pragma unroll
        for (int i = 0; i < NCH; ++i) {
            acc[i] = fma2(cre[i], aC[i], acc[i]);
            acc[i] = fma2(cim[i], aS[i], acc[i]);
            // jump 8 columns: phasor *= (s+it)^8, rm *= rho^8
            u64 nr = fma2(mul2(cim[i], p8i[i]), negone, mul2(cre[i], p8r[i]));
            u64 ni = fma2(cim[i], p8r[i], mul2(cre[i], p8i[i]));
            cre[i] = nr; cim[i] = ni;
            rm[i] = mul2(rm[i], rho8[i]);
        }
    }

    // tail column m = 64 (j==0 lanes are exactly at m=64 now)
    if (j == 0) {
        const u64* tp = (const u64*)(smem + TAIL_OFF);
        u64 c64 = tp[0], s64 = tp[1], dg64 = tp[2];
        #pragma unroll
        for (int i = 0; i < NCH; ++i) {
            u64 b = mul2(rm[i], dg64);
            acc[i] = fma2(cre[i], mul2(b, c64), acc[i]);
            acc[i] = fma2(cim[i], mul2(b, s64), acc[i]);
        }
    }

    // combine 8 column-set partials within each lane-octet
    #pragma unroll
    for (int i = 0; i < NCH; ++i) {
        u64 a = acc[i];
        a = add2(a, __shfl_xor_sync(0xffffffffu, a, 1));
        a = add2(a, __shfl_xor_sync(0xffffffffu, a, 2));
        a = add2(a, __shfl_xor_sync(0xffffffffu, a, 4));
        acc[i] = a;
    }

    if (valid && j == 0) {
        #pragma unroll
        for (int i = 0; i < NCH; ++i) {
            float lo, hi;
            unpack2(acc[i], lo, hi);
            out[4 * q + i] = make_float2(-lo, -hi);
        }
    }
}

// ---------------------------------------------------------------------------
extern "C" void kernel_launch(void* const* d_in, const int* in_sizes, int n_in,
                              void* d_out, int out_size)
{
    const float* inputs = (const float*)d_in[0];  // [B,4] : r,s,t,u
    const float* cBar   = (const float*)d_in[1];  // [67,67]
    const float* sBar   = (const float*)d_in[2];  // [67,67]
    float*       out    = (float*)d_out;          // [B]

    int B    = in_sizes[0] / 4;
    int octs = B / 8;                             // 8192 point-octets

    cudaFuncSetAttribute(pines_kernel,
                         cudaFuncAttributeMaxDynamicSharedMemorySize,
                         SMEM_BYTES);

    int threads_total = octs * 8;                 // 65536
    int blocks = (threads_total + TPB - 1) / TPB; // 147
    pines_kernel<<<blocks, TPB, SMEM_BYTES>>>(
        (const float4*)inputs, cBar, sBar, (float2*)out, octs);
}